// round 1
// baseline (speedup 1.0000x reference)
#include <cuda_runtime.h>
#include <math.h>

#define B_MAX 8192

// Scratch (no cudaMalloc allowed) — zero-initialized at module load,
// explicitly re-zeroed by init_kernel every launch (graph replays).
__device__ float  g_pos[B_MAX];   // (m - pred) for label==1
__device__ float  g_neg[B_MAX];   // pred for label==0
__device__ int    g_n1, g_n0;
__device__ double g_bce;
__device__ double g_hinge;

__device__ __forceinline__ float read_margin(const void* p) {
    // margin is a python int scalar; hedge across int32/int64/float32 encodings.
    int iv = *(const int*)p;
    if (iv >= -1000000 && iv <= 1000000) return (float)iv;  // int32 or low word of int64
    return *(const float*)p;                                 // was actually float bits
}

__global__ void init_kernel() {
    g_n1 = 0; g_n0 = 0; g_bce = 0.0; g_hinge = 0.0;
}

__global__ void bce_compact_kernel(const float* __restrict__ preds,
                                   const float* __restrict__ labels,
                                   const float* __restrict__ logits,
                                   const float* __restrict__ targets,
                                   const float* __restrict__ pos_weight,
                                   const void* __restrict__ margin_ptr,
                                   int n) {
    int i = blockIdx.x * blockDim.x + threadIdx.x;
    float bce = 0.f;
    if (i < n) {
        float x  = logits[i];
        float t  = targets[i];
        float pw = pos_weight[0];
        float mv = fmaxf(-x, 0.f);
        float lw = 1.f + (pw - 1.f) * t;
        bce = (1.f - t) * x + lw * (logf(expf(-mv) + expf(-x - mv)) + mv);

        float m = read_margin(margin_ptr);
        float p = preds[i];
        if (labels[i] > 0.5f) {
            int idx = atomicAdd(&g_n1, 1);
            g_pos[idx] = m - p;          // hinge arg precomputed: max(0, (m-p) + q)
        } else {
            int idx = atomicAdd(&g_n0, 1);
            g_neg[idx] = p;
        }
    }
    // warp-reduce bce, then one double atomic per warp
    #pragma unroll
    for (int o = 16; o; o >>= 1) bce += __shfl_down_sync(0xffffffffu, bce, o);
    if ((threadIdx.x & 31) == 0) atomicAdd(&g_bce, (double)bce);
}

#define PAIR_BLOCKS  128
#define PAIR_THREADS 256
#define MAX_CHUNK    64   // ceil(8192 / PAIR_BLOCKS)

__global__ void __launch_bounds__(PAIR_THREADS)
pair_kernel() {
    __shared__ float s_neg[MAX_CHUNK];
    __shared__ float s_warp[PAIR_THREADS / 32];

    const int n1 = g_n1;
    const int n0 = g_n0;
    const int chunk = (n0 + (int)gridDim.x - 1) / (int)gridDim.x;
    const int start = (int)blockIdx.x * chunk;
    int cnt = n0 - start;
    if (cnt > chunk) cnt = chunk;
    if (cnt < 0) cnt = 0;

    for (int j = threadIdx.x; j < cnt; j += blockDim.x)
        s_neg[j] = g_neg[start + j];
    __syncthreads();

    float acc = 0.f;
    if (cnt > 0) {
        // each thread carries 4 positives in registers; inner loop broadcasts
        // one negative from smem to all lanes (conflict-free broadcast).
        for (int base = (int)threadIdx.x * 4; base < n1; base += (int)blockDim.x * 4) {
            float a0 = (base + 0 < n1) ? g_pos[base + 0] : -1e30f;
            float a1 = (base + 1 < n1) ? g_pos[base + 1] : -1e30f;
            float a2 = (base + 2 < n1) ? g_pos[base + 2] : -1e30f;
            float a3 = (base + 3 < n1) ? g_pos[base + 3] : -1e30f;
            #pragma unroll 8
            for (int j = 0; j < cnt; j++) {
                float q = s_neg[j];
                acc += fmaxf(a0 + q, 0.f);
                acc += fmaxf(a1 + q, 0.f);
                acc += fmaxf(a2 + q, 0.f);
                acc += fmaxf(a3 + q, 0.f);
            }
        }
    }

    // block reduce
    #pragma unroll
    for (int o = 16; o; o >>= 1) acc += __shfl_down_sync(0xffffffffu, acc, o);
    int lane = threadIdx.x & 31, wid = threadIdx.x >> 5;
    if (lane == 0) s_warp[wid] = acc;
    __syncthreads();
    if (threadIdx.x == 0) {
        float s = 0.f;
        #pragma unroll
        for (int w = 0; w < PAIR_THREADS / 32; w++) s += s_warp[w];
        atomicAdd(&g_hinge, (double)s);
    }
}

__global__ void finalize_kernel(const void* __restrict__ margin_ptr,
                                float* __restrict__ out, int n) {
    long long n1 = g_n1, n0 = g_n0;
    double c_same = 0.5 * (double)(n1 * (n1 - 1)) + 0.5 * (double)(n0 * (n0 - 1));
    double m = (double)read_margin(margin_ptr);
    // same-label pairs: prod==0, active iff 0 < m, each contributes m
    double same = (m > 0.0) ? c_same * m : 0.0;
    out[0] = (float)((same + g_hinge) / (double)n);
    out[1] = (float)(g_bce / (double)n);
}

extern "C" void kernel_launch(void* const* d_in, const int* in_sizes, int n_in,
                              void* d_out, int out_size) {
    const float* preds      = (const float*)d_in[0];
    const float* labels     = (const float*)d_in[1];
    const float* logits     = (const float*)d_in[2];
    const float* targets    = (const float*)d_in[3];
    const float* pos_weight = (const float*)d_in[4];
    const void*  margin     = d_in[5];
    float* out = (float*)d_out;
    int n = in_sizes[0];

    init_kernel<<<1, 1>>>();
    bce_compact_kernel<<<(n + 255) / 256, 256>>>(preds, labels, logits, targets,
                                                 pos_weight, margin, n);
    pair_kernel<<<PAIR_BLOCKS, PAIR_THREADS>>>();
    finalize_kernel<<<1, 1>>>(margin, out, n);
}